// round 12
// baseline (speedup 1.0000x reference)
#include <cuda_runtime.h>
#include <cuda_fp16.h>

#define RES     96
#define CENTERF 48.0f
#define EPSF    1e-5f
#define KPMAX   (RES * RES / 2)      // 4608 packed 2-source records
#define RIM2    2209.0f              // 47^2
#define NTW     144                  // 48 i-pairs x 3 windows

// Global scratch (static — no cudaMalloc).
__device__ float        g_part[NTW * 2 * 64];   // 2 K-halves x 64 targets per tile
__device__ unsigned int g_tick[NTW];            // monotone tickets (replay-safe)

// ---------------------------------------------------------------------------
// Grid 288 = 48 i-pairs x 3 adaptive windows x 2 K-halves.
// Block 1024 threads, __launch_bounds__(1024, 2) -> 2 blocks/SM (regs <= 32),
// 64 warps/SM: doubles scheduler-resident warps to hide LDS/MUFU latency.
//
// Record k = sources (2k, 2k+1): uint4 { h2(-bi0,-bi1), h2(bj0,bj1),
// h2(w0,w1), 0 }.  Per record per lane -> 4 terms (2 sources x 2 rows):
//   dj2=fj2-bj2  di0=fi0+nbi2  di1=fi1+nbi2
//   den0=hfma2(di0,di0,hfma2(dj2,dj2,c0))  den1=hfma2(di1,di1,hfma2(dj2,dj2,c1))
//   acc0+=w2*h2rcp(den0)  acc1+=w2*h2rcp(den1)   (flushed to f32 every 4)
// The 2*eps*sqrt(d2) cross term of the reference is dropped
// (relative contribution <= eps/z <= 1e-5 for interior targets).
// K-halves combined by the 2nd-arriving block per tile (fixed order).
// ---------------------------------------------------------------------------
__global__ void __launch_bounds__(1024, 2) fused_kernel(
    const float* __restrict__ b, float* __restrict__ out)
{
    extern __shared__ uint4 ent[];           // KPMAX records, 73728 B dynamic
    __shared__ int   cnts[RES];
    __shared__ int   offs[RES];
    __shared__ int   sK;
    __shared__ float red[32 * 64];
    __shared__ int   sflag;

    const int tid  = threadIdx.x;
    const int wid  = tid >> 5;
    const int lane = tid & 31;

    // ---------------- Phase 0: zero records (tail safety) ----------------
    for (int t = tid; t < KPMAX; t += 1024)
        ent[t] = make_uint4(0u, 0u, 0u, 0u);

    // ---------------- Phase 1: compaction ----------------
    {
        const int r0 = wid * 3;
        #pragma unroll
        for (int rr = 0; rr < 3; rr++) {
            const int row = r0 + rr;
            int c = 0;
            #pragma unroll
            for (int s = 0; s < 3; s++) {
                float v = b[row * RES + s * 32 + lane];
                c += __popc(__ballot_sync(0xffffffffu, v > 0.0f));
            }
            if (lane == 0) cnts[row] = c;
        }
    }
    __syncthreads();
    if (wid == 0) {  // exclusive prefix over 96 row counts
        int a0 = cnts[lane], a1 = cnts[lane + 32], a2 = cnts[lane + 64];
        int s0 = a0, s1 = a1, s2 = a2;
        #pragma unroll
        for (int d = 1; d < 32; d <<= 1) {
            int t0 = __shfl_up_sync(0xffffffffu, s0, d); if (lane >= d) s0 += t0;
            int t1 = __shfl_up_sync(0xffffffffu, s1, d); if (lane >= d) s1 += t1;
            int t2 = __shfl_up_sync(0xffffffffu, s2, d); if (lane >= d) s2 += t2;
        }
        s1 += __shfl_sync(0xffffffffu, s0, 31);
        s2 += __shfl_sync(0xffffffffu, s1, 31);
        offs[lane]      = s0 - a0;
        offs[lane + 32] = s1 - a1;
        offs[lane + 64] = s2 - a2;
        if (lane == 31) sK = s2;
    }
    __syncthreads();
    {   // scatter: element pos -> record pos>>1, half-lane pos&1
        const int r0 = wid * 3;
        #pragma unroll
        for (int rr = 0; rr < 3; rr++) {
            const int row = r0 + rr;
            int p = offs[row];
            #pragma unroll
            for (int s = 0; s < 3; s++) {
                const int col = s * 32 + lane;
                float v = b[row * RES + col];
                unsigned m = __ballot_sync(0xffffffffu, v > 0.0f);
                if (v > 0.0f) {
                    int pos = p + __popc(m & ((1u << lane) - 1u));
                    __half* hp = reinterpret_cast<__half*>(&ent[pos >> 1]);
                    const int o = pos & 1;
                    hp[0 + o] = __float2half_rn(-(float)row);
                    hp[2 + o] = __float2half_rn((float)col);
                    hp[4 + o] = __float2half_rn(v);
                }
                p += __popc(m);
            }
        }
    }
    __syncthreads();

    // ---------------- window placement ----------------
    const int pp  = blockIdx.x / 6;               // i-pair 0..47
    const int rem = blockIdx.x % 6;
    const int g   = rem >> 1;                     // window 0..2
    const int h   = rem & 1;                      // K-half
    const int tw  = pp * 3 + g;                   // tile id 0..143
    const int i0  = 2 * pp;

    const int a0i = abs(i0 - 48);
    const int a1i = abs(i0 + 1 - 48);
    const int dmin = a0i < a1i ? a0i : a1i;
    int s_ = 2208 - dmin * dmin; if (s_ < 0) s_ = 0;
    const int wmax = (int)sqrtf((float)s_) + 1;   // over-estimate: safe
    int J0 = 48 - wmax; if (J0 < 0) J0 = 0;

    const int j   = J0 + 32 * g + lane;           // may exceed 95 (guarded)
    const float fi0 = (float)i0;
    const float fj  = (float)j;

    const float dic0 = fi0 - CENTERF;
    const float dic1 = dic0 + 1.0f;
    const float djc  = fj - CENTERF;
    const float r2_0 = dic0 * dic0 + djc * djc;   // exact integer-valued
    const float r2_1 = dic1 * dic1 + djc * djc;
    const float z0 = CENTERF - sqrtf(r2_0) + EPSF;
    const float z1 = CENTERF - sqrtf(r2_1) + EPSF;
    const float c00 = fmaf(z0, z0, EPSF * EPSF);
    const float c01 = fmaf(z1, z1, EPSF * EPSF);

    const __half2 c0_2  = __half2half2(__float2half_rn(c00));
    const __half2 c1_2  = __half2half2(__float2half_rn(c01));
    const __half2 fi0_2 = __half2half2(__float2half_rn(fi0));
    const __half2 fi1_2 = __half2half2(__float2half_rn(fi0 + 1.0f));
    const __half2 fj2   = __half2half2(__float2half_rn(fj));
    const __half2 zero2 = __floats2half2_rn(0.0f, 0.0f);

    const bool allrim = __all_sync(0xffffffffu,
                                   (r2_0 >= RIM2) && (r2_1 >= RIM2));
    const int Kp = (sK + 1) >> 1;
    const int pa = (Kp * h) >> 1;
    const int pb = (Kp * (h + 1)) >> 1;
    float f0 = 0.0f, f1 = 0.0f;

    // ---------------- Phase 2: f16x2 core over this block's K-half ----------
    if (!allrim) {
        __half2 acc0 = zero2, acc1 = zero2;
        const int n = pb - pa;
        const int nfull = (n > wid) ? (n - wid + 31) / 32 : 0;
        const int nb4 = nfull >> 2;
        const uint4* pe = ent + pa + wid;

        for (int b4 = 0; b4 < nb4; b4++) {
            #pragma unroll
            for (int u = 0; u < 4; u++) {
                uint4 e = pe[u * 32];                     // LDS.128 imm offset
                __half2 nbi2 = *reinterpret_cast<__half2*>(&e.x);
                __half2 bj2  = *reinterpret_cast<__half2*>(&e.y);
                __half2 w2   = *reinterpret_cast<__half2*>(&e.z);
                __half2 dj2  = __hsub2(fj2, bj2);
                __half2 di0  = __hadd2(fi0_2, nbi2);
                __half2 di1  = __hadd2(fi1_2, nbi2);
                __half2 den0 = __hfma2(di0, di0, __hfma2(dj2, dj2, c0_2));
                __half2 den1 = __hfma2(di1, di1, __hfma2(dj2, dj2, c1_2));
                acc0 = __hfma2(w2, h2rcp(den0), acc0);
                acc1 = __hfma2(w2, h2rcp(den1), acc1);
            }
            pe += 128;
            f0 += __low2float(acc0) + __high2float(acc0);
            f1 += __low2float(acc1) + __high2float(acc1);
            acc0 = zero2; acc1 = zero2;
        }
        for (int r = nb4 * 4; r < nfull; r++) {
            uint4 e = *pe; pe += 32;
            __half2 nbi2 = *reinterpret_cast<__half2*>(&e.x);
            __half2 bj2  = *reinterpret_cast<__half2*>(&e.y);
            __half2 w2   = *reinterpret_cast<__half2*>(&e.z);
            __half2 dj2  = __hsub2(fj2, bj2);
            __half2 di0  = __hadd2(fi0_2, nbi2);
            __half2 di1  = __hadd2(fi1_2, nbi2);
            __half2 den0 = __hfma2(di0, di0, __hfma2(dj2, dj2, c0_2));
            __half2 den1 = __hfma2(di1, di1, __hfma2(dj2, dj2, c1_2));
            acc0 = __hfma2(w2, h2rcp(den0), acc0);
            acc1 = __hfma2(w2, h2rcp(den1), acc1);
        }
        f0 += __low2float(acc0) + __high2float(acc0);
        f1 += __low2float(acc1) + __high2float(acc1);
    }

    red[wid * 64 + lane]      = f0;
    red[wid * 64 + 32 + lane] = f1;
    __syncthreads();

    // ---------------- Phase 3: block reduce -> global partial ----------------
    if (tid < 64) {
        float s = 0.0f;
        #pragma unroll 8
        for (int w = 0; w < 32; w++) s += red[w * 64 + tid];
        g_part[(tw * 2 + h) * 64 + tid] = s;
    }

    // rim passthrough for uncovered columns j < J0 (one block per pair)
    if (g == 0 && h == 0 && tid < RES && tid < J0) {
        out[i0 * RES + tid]       = b[i0 * RES + tid];
        out[(i0 + 1) * RES + tid] = b[(i0 + 1) * RES + tid];
    }

    __threadfence();                              // publish partial (gpu scope)
    __syncthreads();
    if (tid == 0) {
        unsigned old = atomicAdd(&g_tick[tw], 1u);
        sflag = ((old & 1u) == 1u);               // 2nd arrival this launch
        __threadfence();                          // acquire side
    }
    __syncthreads();

    // ---- 2nd-arriving block combines both K-halves (fixed order) & writes ----
    if (sflag && tid < 64) {
        float s = __ldcg(&g_part[(tw * 2 + 0) * 64 + tid])
                + __ldcg(&g_part[(tw * 2 + 1) * 64 + tid]);
        const int k  = tid >> 5;
        const int l  = tid & 31;
        const int ii = i0 + k;
        const int jj = J0 + 32 * g + l;
        if (jj < RES) {
            const int di = ii - 48, dj = jj - 48;
            const float bv = b[ii * RES + jj];
            out[ii * RES + jj] = (di * di + dj * dj >= 2209) ? bv : s;
        }
    }
}

// ---------------------------------------------------------------------------
extern "C" void kernel_launch(void* const* d_in, const int* in_sizes, int n_in,
                              void* d_out, int out_size) {
    (void)in_sizes; (void)n_in; (void)out_size;
    const float* b   = (const float*)d_in[0];
    float*       out = (float*)d_out;

    const int smem_bytes = KPMAX * (int)sizeof(uint4);  // 73728
    cudaFuncSetAttribute(fused_kernel,
                         cudaFuncAttributeMaxDynamicSharedMemorySize, smem_bytes);

    fused_kernel<<<288, 1024, smem_bytes>>>(b, out);
}